// round 14
// baseline (speedup 1.0000x reference)
#include <cuda_runtime.h>
#include <cuda_fp16.h>
#include <cstdint>
#include <math.h>

#define NB 16
#define NN 1024
#define HH 256
#define LH 768          // H*(1+L) = 768
#define NBLK 256        // sinkhorn persistent grid

// ---------------- scratch (__device__ globals; no cudaMalloc allowed) ----------------
__device__ float g_hall[(size_t)NB * 4 * NN * HH];   // [b][c][n][h]
__device__ float g_hcat[(size_t)NB * NN * LH];       // [b*n][768]  (h0|h1|h2)
__device__ float g_t0[(size_t)NB * NN * HH];
__device__ float g_t1[(size_t)NB * NN * HH];
__device__ float g_t2[(size_t)NB * NN * HH];
__device__ float g_dis[NB * NN];
__device__ float g_rsinv[NB * NN];
__device__ float g_u[NB * NN];
__device__ float g_v[NB * NN];
__device__ float g_r[NB * NN];
__device__ float g_c[NB * NN];

// fp16 split operands
__device__ __half g_adjH[(size_t)NB * NN * NN];
__device__ __half g_adjL[(size_t)NB * NN * NN];
__device__ __half g_xlH[(size_t)NB * NN * HH];
__device__ __half g_xlL[(size_t)NB * NN * HH];
__device__ __half g_xsH[(size_t)NB * NN * HH];
__device__ __half g_xsL[(size_t)NB * NN * HH];
__device__ __half g_p0H[(size_t)NB * NN * HH];
__device__ __half g_p0L[(size_t)NB * NN * HH];
__device__ __half g_p1H[(size_t)NB * NN * HH];
__device__ __half g_p1L[(size_t)NB * NN * HH];
__device__ __half g_p2H[(size_t)NB * NN * HH];
__device__ __half g_p2L[(size_t)NB * NN * HH];

// fp16 pairs for dense pipeline (+ w_in pack + X pair)
__device__ __half g_wH[753664];
__device__ __half g_wL[753664];
__device__ __half g_xinH[(size_t)NB * NN * 128];
__device__ __half g_xinL[(size_t)NB * NN * 128];
__device__ __half g_hpH[(size_t)NB * NN * HH];
__device__ __half g_hpL[(size_t)NB * NN * HH];
__device__ __half g_htH[(size_t)NB * NN * HH];
__device__ __half g_htL[(size_t)NB * NN * HH];
__device__ __half g_m1H[(size_t)NB * NN * HH];
__device__ __half g_m1L[(size_t)NB * NN * HH];
__device__ __half g_hcH[(size_t)NB * NN * LH];
__device__ __half g_hcL[(size_t)NB * NN * LH];

// per-batch sinkhorn barrier: monotonic arrival counters, reset by prep_adj each call
__device__ unsigned g_arr[16];

#define BSCALE 256.0f
#define BINV   (1.0f / 256.0f)
#define ACCINV (1.0f / 65536.0f)

// weight pack offsets
#define OW_CW1 0
#define OW_CW2 131072
#define OW_M1W 262144
#define OW_M2W 458752
#define OW_WIN 720896
#define W_TOTAL 753664
#define X_TOTAL 2097152

// ---------------- helpers ----------------
__device__ __forceinline__ float lky(float x) { return x > 0.0f ? x : 0.01f * x; }

__device__ __forceinline__ float warpSum(float v) {
    #pragma unroll
    for (int o = 16; o; o >>= 1) v += __shfl_xor_sync(0xffffffffu, v, o);
    return v;
}
__device__ __forceinline__ float warpMax(float v) {
    #pragma unroll
    for (int o = 16; o; o >>= 1) v = fmaxf(v, __shfl_xor_sync(0xffffffffu, v, o));
    return v;
}

__device__ __forceinline__ uint32_t rotl_(uint32_t v, int s) { return (v << s) | (v >> (32 - s)); }

// Threefry-2x32 with key = (0, 42)
__device__ __forceinline__ void threefry_42(uint32_t x0, uint32_t x1, uint32_t& o0, uint32_t& o1) {
    const uint32_t k0 = 0u, k1 = 42u;
    const uint32_t k2 = 0u ^ 42u ^ 0x1BD11BDAu;
    x0 += k0; x1 += k1;
#define TF4(a,b,c,d, ka, kb, inc)                     \
    x0 += x1; x1 = rotl_(x1, a); x1 ^= x0;            \
    x0 += x1; x1 = rotl_(x1, b); x1 ^= x0;            \
    x0 += x1; x1 = rotl_(x1, c); x1 ^= x0;            \
    x0 += x1; x1 = rotl_(x1, d); x1 ^= x0;            \
    x0 += ka; x1 += kb + inc;
    TF4(13, 15, 26, 6,  k1, k2, 1u)
    TF4(17, 29, 16, 24, k2, k0, 2u)
    TF4(13, 15, 26, 6,  k0, k1, 3u)
    TF4(17, 29, 16, 24, k1, k2, 4u)
    TF4(13, 15, 26, 6,  k2, k0, 5u)
#undef TF4
    o0 = x0; o1 = x1;
}

__device__ __forceinline__ float gumbel_noise(uint32_t idx) {
    uint32_t o0, o1;
    threefry_42(0u, idx, o0, o1);
    uint32_t bits = o0 ^ o1;
    float u = __uint_as_float((bits >> 9) | 0x3f800000u) - 1.0f;
    return -logf(-logf(u + 1e-20f) + 1e-20f) * 0.05f;
}

// per-batch grid barrier: monotonic counter; k = barrier index (starts at 1)
__device__ __forceinline__ void gridbar_b(int b, unsigned& k) {
    __syncthreads();
    if (threadIdx.x == 0) {
        __threadfence();
        atomicAdd(&g_arr[b], 1u);
        unsigned target = 16u * k;
        while (*(volatile unsigned*)&g_arr[b] < target) { }
        __threadfence();
    }
    __syncthreads();
    k++;
}

// ---------------- async / mma primitives ----------------
__device__ __forceinline__ uint32_t s2u(const void* p) {
    return (uint32_t)__cvta_generic_to_shared(p);
}
__device__ __forceinline__ void cpa16(uint32_t s, const void* g) {
    asm volatile("cp.async.cg.shared.global [%0], [%1], 16;" :: "r"(s), "l"(g));
}
__device__ __forceinline__ void cpa_commit() {
    asm volatile("cp.async.commit_group;" ::: "memory");
}
template<int N>
__device__ __forceinline__ void cpa_wait() {
    asm volatile("cp.async.wait_group %0;" :: "n"(N) : "memory");
}
__device__ __forceinline__ void ldmA4(uint32_t a, uint32_t* r) {
    asm volatile("ldmatrix.sync.aligned.m8n8.x4.shared.b16 {%0,%1,%2,%3}, [%4];"
        : "=r"(r[0]), "=r"(r[1]), "=r"(r[2]), "=r"(r[3]) : "r"(a));
}
__device__ __forceinline__ void ldmB4T(uint32_t a, uint32_t* r) {
    asm volatile("ldmatrix.sync.aligned.m8n8.x4.trans.shared.b16 {%0,%1,%2,%3}, [%4];"
        : "=r"(r[0]), "=r"(r[1]), "=r"(r[2]), "=r"(r[3]) : "r"(a));
}
__device__ __forceinline__ void mma16816(float* d, const uint32_t* A, const uint32_t* b) {
    asm volatile("mma.sync.aligned.m16n8k16.row.col.f32.f16.f16.f32 "
        "{%0,%1,%2,%3},{%4,%5,%6,%7},{%8,%9},{%0,%1,%2,%3};"
        : "+f"(d[0]), "+f"(d[1]), "+f"(d[2]), "+f"(d[3])
        : "r"(A[0]), "r"(A[1]), "r"(A[2]), "r"(A[3]), "r"(b[0]), "r"(b[1]));
}

// ---------------- fused adj prep: rowsum + fp16 hi/lo conversion + barrier reset ----------------
__global__ void prep_adj(const float* __restrict__ adj,
                         __half* __restrict__ aH, __half* __restrict__ aL,
                         float* __restrict__ dis, float* __restrict__ rsinv) {
    int gr = blockIdx.x, t = threadIdx.x;
    if (gr == 0 && t < 16) g_arr[t] = 0u;    // reset sinkhorn barrier counters (stream-ordered)
    const float* rowp = adj + ((size_t)gr << 10);
    float4 a4 = ((const float4*)rowp)[t];
    __half2 h01 = __floats2half2_rn(a4.x, a4.y);
    __half2 h23 = __floats2half2_rn(a4.z, a4.w);
    __half2 l01 = __floats2half2_rn(a4.x - __low2float(h01), a4.y - __high2float(h01));
    __half2 l23 = __floats2half2_rn(a4.z - __low2float(h23), a4.w - __high2float(h23));
    size_t hb = ((size_t)gr << 9) + ((size_t)t << 1);
    ((__half2*)aH)[hb]     = h01;
    ((__half2*)aH)[hb + 1] = h23;
    ((__half2*)aL)[hb]     = l01;
    ((__half2*)aL)[hb + 1] = l23;
    float s = a4.x + a4.y + a4.z + a4.w;
    s = warpSum(s);
    __shared__ float sm[8];
    if ((t & 31) == 0) sm[t >> 5] = s;
    __syncthreads();
    if (t == 0) {
        float S = sm[0] + sm[1] + sm[2] + sm[3] + sm[4] + sm[5] + sm[6] + sm[7];
        dis[gr]   = rsqrtf(S + 1.0f);
        rsinv[gr] = 1.0f / S;
    }
}

// all weights (incl w_in) + input X -> scaled fp16 pairs, single launch
__global__ void convert_all(const float* __restrict__ cw1, const float* __restrict__ cw2,
                            const float* __restrict__ m1w, const float* __restrict__ m2w,
                            const float* __restrict__ w_in, const float* __restrict__ X,
                            __half* __restrict__ H, __half* __restrict__ L,
                            __half* __restrict__ xinH, __half* __restrict__ xinL) {
    int i = blockIdx.x * 256 + threadIdx.x;
    if (i < W_TOTAL) {
        float x;
        if (i < 131072)      x = cw1[i];
        else if (i < 262144) x = cw2[i - 131072];
        else if (i < 458752) x = m1w[i - 262144];
        else if (i < 720896) x = m2w[i - 458752];
        else                 x = w_in[i - 720896];
        x *= BSCALE;
        __half h = __float2half_rn(x);
        H[i] = h;
        L[i] = __float2half_rn(x - __half2float(h));
    } else {
        int j = i - W_TOTAL;
        float x = X[j] * BSCALE;
        __half h = __float2half_rn(x);
        xinH[j] = h;
        xinL[j] = __float2half_rn(x - __half2float(h));
    }
}

// ---------------- tensor-core adjacency GEMM (2-stage, single sync/chunk, occ 2) ----------------
// MODE 1: applyP + diff; MODE 2: applyP plain;
// MODE 3: fused GCN (blockIdx.x<2, B=bH/bL) + applyP-diff (blockIdx.x>=2, B=bH2/bL2).
#define ADJ_STG 37888
#define SMEM_A  (2 * ADJ_STG)

template<int MODE>
__global__ void __launch_bounds__(256, 2)
adjmma(const __half* __restrict__ adjH, const __half* __restrict__ adjL,
       const __half* __restrict__ bH, const __half* __restrict__ bL,
       const __half* __restrict__ bH2, const __half* __restrict__ bL2,
       const float* __restrict__ U32, int ldu,
       const float* __restrict__ aux, int ldaux,
       const float* __restrict__ dis, const float* __restrict__ rsinv,
       float* __restrict__ pout, int ldp,
       __half* __restrict__ poutH, __half* __restrict__ poutL,
       float* __restrict__ hallc, float* __restrict__ hallc2) {
    extern __shared__ char smx[];
    const uint32_t sbase = s2u(smx);
    const int t = threadIdx.x;
    const int b = blockIdx.z;
    const int m0 = blockIdx.y << 7;
    const int sel = (MODE == 3) ? ((int)blockIdx.x >> 1) : 0;
    const int n0 = ((MODE == 3) ? ((int)blockIdx.x & 1) : (int)blockIdx.x) << 7;
    const __half* BHp = (MODE == 3 && sel) ? bH2 : bH;
    const __half* BLp = (MODE == 3 && sel) ? bL2 : bL;
    const int w = t >> 5, lane = t & 31;
    const int wm = w >> 1, wn = w & 1;
    const int lr16 = lane & 15, lhi = lane >> 4;

    float acc[2][8][4];
    #pragma unroll
    for (int mi = 0; mi < 2; mi++)
        #pragma unroll
        for (int nj = 0; nj < 8; nj++)
            #pragma unroll
            for (int ci = 0; ci < 4; ci++) acc[mi][nj][ci] = 0.0f;

    const int ar = t >> 2,  asg = t & 3;
    const int bk = t >> 4,  bsg = t & 15;

    auto issue = [&](int kt, int st) {
        uint32_t AHb = sbase + st * ADJ_STG;
        uint32_t ALb = AHb + 10240;
        uint32_t BHb = ALb + 10240;
        uint32_t BLb = BHb + 8704;
        #pragma unroll
        for (int it = 0; it < 2; it++) {
            int r = ar + (it << 6);
            size_t gA = ((size_t)b << 20) + ((size_t)(m0 + r) << 10) + (kt << 5) + (asg << 3);
            uint32_t sA = (uint32_t)(r * 80 + (asg << 4));
            cpa16(AHb + sA, adjH + gA);
            cpa16(ALb + sA, adjL + gA);
            int k = bk + (it << 4);
            size_t gB = ((size_t)((b << 10) + (kt << 5) + k) << 8) + n0 + (bsg << 3);
            uint32_t sB = (uint32_t)(k * 272 + (bsg << 4));
            cpa16(BHb + sB, BHp + gB);
            cpa16(BLb + sB, BLp + gB);
        }
        cpa_commit();
    };

    issue(0, 0);
    for (int kt = 0; kt < 32; kt++) {
        cpa_wait<0>();
        __syncthreads();
        if (kt + 1 < 32) issue(kt + 1, (kt + 1) & 1);

        int st = kt & 1;
        uint32_t AHb = sbase + st * ADJ_STG;
        uint32_t ALb = AHb + 10240;
        uint32_t BHb = ALb + 10240;
        uint32_t BLb = BHb + 8704;

        #pragma unroll
        for (int kk = 0; kk < 32; kk += 16) {
            uint32_t aHf[2][4], aLf[2][4];
            uint32_t cc2 = (uint32_t)((kk + (lhi << 3)) << 1);
            #pragma unroll
            for (int mi = 0; mi < 2; mi++) {
                uint32_t ro = (uint32_t)((wm * 32 + mi * 16 + lr16) * 80);
                ldmA4(AHb + ro + cc2, aHf[mi]);
                ldmA4(ALb + ro + cc2, aLf[mi]);
            }
            #pragma unroll
            for (int hf = 0; hf < 2; hf++) {
                uint32_t bHf[4][2], bLf[4][2];
                #pragma unroll
                for (int np = 0; np < 2; np++) {
                    uint32_t ko = (uint32_t)((kk + lr16) * 272);
                    uint32_t nc = (uint32_t)((wn * 64 + hf * 32 + np * 16 + (lhi << 3)) << 1);
                    uint32_t r4[4];
                    ldmB4T(BHb + ko + nc, r4);
                    bHf[np*2][0] = r4[0]; bHf[np*2][1] = r4[1];
                    bHf[np*2+1][0] = r4[2]; bHf[np*2+1][1] = r4[3];
                    ldmB4T(BLb + ko + nc, r4);
                    bLf[np*2][0] = r4[0]; bLf[np*2][1] = r4[1];
                    bLf[np*2+1][0] = r4[2]; bLf[np*2+1][1] = r4[3];
                }
                #pragma unroll
                for (int mi = 0; mi < 2; mi++)
                    #pragma unroll
                    for (int nj = 0; nj < 4; nj++) {
                        float* ac = acc[mi][hf * 4 + nj];
                        mma16816(ac, aHf[mi], bHf[nj]);
                        mma16816(ac, aHf[mi], bLf[nj]);
                        mma16816(ac, aLf[mi], bHf[nj]);
                    }
            }
        }
    }

    const int g8 = lane >> 2, t4 = lane & 3;
    #pragma unroll
    for (int mi = 0; mi < 2; mi++)
        #pragma unroll
        for (int nj = 0; nj < 8; nj++)
            #pragma unroll
            for (int ci = 0; ci < 4; ci++) {
                int il = m0 + wm * 32 + mi * 16 + g8 + ((ci >> 1) << 3);
                int cg = n0 + wn * 64 + nj * 8 + (t4 << 1) + (ci & 1);
                int gi = (b << 10) + il;
                float a = acc[mi][nj][ci] * BINV;
                size_t hix = ((size_t)b << 20) + ((size_t)il << 8) + cg;
                if (MODE == 3 && sel == 0) {
                    float di = dis[gi];
                    float xv = aux[(size_t)gi * ldaux + cg];
                    hallc[hix] = lky(di * a + di * di * xv);
                } else {
                    float p = 0.5f * (U32[(size_t)gi * ldu + cg] + rsinv[gi] * a);
                    pout[(size_t)gi * ldp + cg] = p;
                    float ps = p * BSCALE;
                    __half ph = __float2half_rn(ps);
                    size_t pix = ((size_t)gi << 8) + cg;
                    poutH[pix] = ph;
                    poutL[pix] = __float2half_rn(ps - __half2float(ph));
                    if (MODE == 1) {
                        float ax = aux[(size_t)gi * ldaux + cg];
                        hallc[hix] = fabsf(ax - p);
                    } else if (MODE == 3) {
                        float ax = aux[(size_t)gi * ldaux + cg];
                        hallc2[hix] = fabsf(ax - p);
                    }
                }
            }
}

// ---------------- dense HMMA GEMM (single sync/chunk) ----------------
// EP 0: raw out; EP 1: leaky; EP 2: Z0 epilogue.
// EP 0/1 optional: fp32 out(ldo), fp16 pair poH/poL(ldp), xl/xs pairs (ld HH, needs dis).
template<int EP>
__global__ void __launch_bounds__(256, 2)
hgemm(const __half* __restrict__ AH, const __half* __restrict__ AL, int lda,
      const __half* __restrict__ WH, const __half* __restrict__ WL, int K,
      const float* __restrict__ bias,
      float* __restrict__ out, int ldo,
      __half* __restrict__ poH, __half* __restrict__ poL, int ldp,
      const float* __restrict__ dis,
      __half* __restrict__ xlH, __half* __restrict__ xlL,
      __half* __restrict__ xsH, __half* __restrict__ xsL,
      float* __restrict__ zbuf) {
    extern __shared__ char smx[];
    const uint32_t sbase = s2u(smx);
    const int t = threadIdx.x;
    const int m0 = blockIdx.y << 7;
    const int n0 = blockIdx.x << 7;
    const int w = t >> 5, lane = t & 31;
    const int wm = w >> 1, wn = w & 1;
    const int lr16 = lane & 15, lhi = lane >> 4;

    float acc[2][8][4];
    #pragma unroll
    for (int mi = 0; mi < 2; mi++)
        #pragma unroll
        for (int nj = 0; nj < 8; nj++)
            #pragma unroll
            for (int ci = 0; ci < 4; ci++) acc[mi][nj][ci] = 0.0f;

    const int lrow = t >> 1, lsg = t & 1;

    auto issue = [&](int kt, int st) {
        uint32_t AHb = sbase + st * 40960;
        uint32_t ALb = AHb + 10240;
        uint32_t WHb = ALb + 10240;
        uint32_t WLb = WHb + 10240;
        uint32_t so = (uint32_t)(lrow * 80 + (lsg << 5));
        size_t gA = (size_t)(m0 + lrow) * lda + (kt << 5) + (lsg << 4);
        size_t gW = (size_t)(n0 + lrow) * K   + (kt << 5) + (lsg << 4);
        cpa16(AHb + so,      AH + gA);
        cpa16(AHb + so + 16, AH + gA + 8);
        cpa16(ALb + so,      AL + gA);
        cpa16(ALb + so + 16, AL + gA + 8);
        cpa16(WHb + so,      WH + gW);
        cpa16(WHb + so + 16, WH + gW + 8);
        cpa16(WLb + so,      WL + gW);
        cpa16(WLb + so + 16, WL + gW + 8);
        cpa_commit();
    };

    const int nchunks = K >> 5;
    issue(0, 0);
    for (int kt = 0; kt < nchunks; kt++) {
        cpa_wait<0>();
        __syncthreads();
        if (kt + 1 < nchunks) issue(kt + 1, (kt + 1) & 1);

        int st = kt & 1;
        uint32_t AHb = sbase + st * 40960;
        uint32_t ALb = AHb + 10240;
        uint32_t WHb = ALb + 10240;
        uint32_t WLb = WHb + 10240;

        #pragma unroll
        for (int kk = 0; kk < 32; kk += 16) {
            uint32_t aHf[2][4], aLf[2][4];
            uint32_t cc2 = (uint32_t)((kk + (lhi << 3)) << 1);
            #pragma unroll
            for (int mi = 0; mi < 2; mi++) {
                uint32_t ro = (uint32_t)((wm * 32 + mi * 16 + lr16) * 80);
                ldmA4(AHb + ro + cc2, aHf[mi]);
                ldmA4(ALb + ro + cc2, aLf[mi]);
            }
            uint32_t nrow = (uint32_t)(((lane >> 4) << 3) + (lane & 7));
            uint32_t kb   = (uint32_t)(kk * 2 + ((lane >> 3) & 1) * 16);
            #pragma unroll
            for (int hf = 0; hf < 2; hf++) {
                uint32_t bHf[4][2], bLf[4][2];
                #pragma unroll
                for (int np = 0; np < 2; np++) {
                    uint32_t ad = (uint32_t)((wn * 64 + hf * 32 + np * 16 + nrow) * 80) + kb;
                    uint32_t r4[4];
                    ldmA4(WHb + ad, r4);
                    bHf[np*2][0] = r4[0]; bHf[np*2][1] = r4[1];
                    bHf[np*2+1][0] = r4[2]; bHf[np*2+1][1] = r4[3];
                    ldmA4(WLb + ad, r4);
                    bLf[np*2][0] = r4[0]; bLf[np*2][1] = r4[1];
                    bLf[np*2+1][0] = r4[2]; bLf[np*2+1][1] = r4[3];
                }
                #pragma unroll
                for (int mi = 0; mi < 2; mi++)
                    #pragma unroll
                    for (int nj = 0; nj < 4; nj++) {
                        float* ac = acc[mi][hf * 4 + nj];
                        mma16816(ac, aHf[mi], bHf[nj]);
                        mma16816(ac, aHf[mi], bLf[nj]);
                        mma16816(ac, aLf[mi], bHf[nj]);
                    }
            }
        }
    }

    const int g8 = lane >> 2, t4 = lane & 3;
    #pragma unroll
    for (int mi = 0; mi < 2; mi++)
        #pragma unroll
        for (int nj = 0; nj < 8; nj++)
            #pragma unroll
            for (int ci = 0; ci < 4; ci++) {
                int rg = m0 + wm * 32 + mi * 16 + g8 + ((ci >> 1) << 3);
                int cg = n0 + wn * 64 + nj * 8 + (t4 << 1) + (ci & 1);
                float v = acc[mi][nj][ci] * ACCINV + __ldg(&bias[cg]);
                if (EP == 2) {
                    uint32_t idx = ((uint32_t)rg << 10) + (uint32_t)cg;
                    float z = (tanhf(v) * 40.0f + gumbel_noise(idx)) * 10.0f;
                    zbuf[idx] = z;
                } else {
                    float o = (EP == 1) ? lky(v) : v;
                    if (out) out[(size_t)rg * ldo + cg] = o;
                    if (poH) {
                        float ps = o * BSCALE;
                        __half ph = __float2half_rn(ps);
                        size_t pix = (size_t)rg * ldp + cg;
                        poH[pix] = ph;
                        poL[pix] = __float2half_rn(ps - __half2float(ph));
                    }
                    if (xlH) {
                        float xl = o * BSCALE;
                        float xs = xl * dis[rg];
                        __half h1 = __float2half_rn(xl);
                        __half h2 = __float2half_rn(xs);
                        size_t gid = ((size_t)rg << 8) + cg;
                        xlH[gid] = h1;
                        xlL[gid] = __float2half_rn(xl - __half2float(h1));
                        xsH[gid] = h2;
                        xsL[gid] = __float2half_rn(xs - __half2float(h2));
                    }
                }
            }
}

// ---------------- attention + channel mix -> hp fp16 pair ----------------
__global__ void attention_kernel(const float* __restrict__ Xl, int ldx,
                                 const float* __restrict__ hall,
                                 const float* __restrict__ a,
                                 __half* __restrict__ hpH, __half* __restrict__ hpL) {
    int n = blockIdx.x, b = blockIdx.y, t = threadIdx.x;
    float xv = Xl[(size_t)((b << 10) + n) * ldx + t];
    float hv[4];
    size_t hbase = ((size_t)b << 20) + ((size_t)n << 8) + t;
    #pragma unroll
    for (int c = 0; c < 4; c++) hv[c] = hall[hbase + ((size_t)c << 18)];
    float a1 = a[t], a2 = a[256 + t];
    float p[5];
    p[0] = fmaxf(xv, 0.0f) * a1;
    #pragma unroll
    for (int c = 0; c < 4; c++) p[1 + c] = fmaxf(hv[c], 0.0f) * a2;

    __shared__ float sm[5][8];
    #pragma unroll
    for (int q = 0; q < 5; q++) {
        float s = warpSum(p[q]);
        if ((t & 31) == 0) sm[q][t >> 5] = s;
    }
    __syncthreads();
    float S[5];
    #pragma unroll
    for (int q = 0; q < 5; q++) {
        float s = sm[q][0];
        #pragma unroll
        for (int w = 1; w < 8; w++) s += sm[q][w];
        S[q] = s;
    }
    float e0 = S[0] + S[1], e1 = S[0] + S[2], e2 = S[0] + S[3], e3 = S[0] + S[4];
    float M = fmaxf(fmaxf(e0, e1), fmaxf(e2, e3));
    float w0 = __expf(e0 - M), w1 = __expf(e1 - M), w2 = __expf(e2 - M), w3 = __expf(e3 - M);
    float ws = w0 + w1 + w2 + w3;
    float o = w0 * hv[0] + w1 * hv[1] + w2 * hv[2] + w3 * hv[3];
    float hpv = 0.25f * o / ws;
    float ps = hpv * BSCALE;
    __half ph = __float2half_rn(ps);
    size_t pix = (size_t)((b << 10) + n) * HH + t;
    hpH[pix] = ph;
    hpL[pix] = __float2half_rn(ps - __half2float(ph));
}

// ---------------- persistent sinkhorn (per-batch monotonic barriers) ----------------
__global__ void __launch_bounds__(256)
sinkhorn_all(const float* __restrict__ Z0, float* __restrict__ P,
             float* __restrict__ u, float* __restrict__ v,
             float* __restrict__ r, float* __restrict__ c) {
    const int t = threadIdx.x;
    const int bid = blockIdx.x;
    const int b = bid >> 4, ch = bid & 15;
    const int lane = t & 31, w = t >> 5;
    __shared__ float vec[1024];
    __shared__ float red[256];
    __shared__ float red2[256];
    unsigned k = 1;

    if (t < 64) {
        u[(b << 10) + (ch << 6) + t] = 0.0f;
        v[(b << 10) + (ch << 6) + t] = 0.0f;
    }
    gridbar_b(b, k);

    const float* zb = Z0 + ((size_t)b << 20);

    for (int it = 0; it < 20; it++) {
        for (int i = t; i < 1024; i += 256) vec[i] = v[(b << 10) + i];
        __syncthreads();
        #pragma unroll 1
        for (int rr = 0; rr < 8; rr++) {
            int row = (ch << 6) + (w << 3) + rr;
            const float* zr = zb + ((size_t)row << 10);
            float a[32];
            float m = -INFINITY;
            #pragma unroll
            for (int q = 0; q < 8; q++) {
                int idx = lane + (q << 5);
                float4 z4 = ((const float4*)zr)[idx];
                int cb = idx << 2;
                a[q*4+0] = z4.x - vec[cb];
                a[q*4+1] = z4.y - vec[cb+1];
                a[q*4+2] = z4.z - vec[cb+2];
                a[q*4+3] = z4.w - vec[cb+3];
                m = fmaxf(m, fmaxf(fmaxf(a[q*4], a[q*4+1]), fmaxf(a[q*4+2], a[q*4+3])));
            }
            m = warpMax(m);
            float s = 0.0f;
            #pragma unroll
            for (int q = 0; q < 32; q++) s += __expf(a[q] - m);
            s = warpSum(s);
            if (lane == 0) u[(b << 10) + row] = m + __logf(s);
        }
        gridbar_b(b, k);

        for (int i = t; i < 1024; i += 256) vec[i] = u[(b << 10) + i];
        __syncthreads();
        {
            int jj = t & 63, seg = t >> 6;
            int j = (ch << 6) + jj;
            float m = -INFINITY, s = 0.0f;
            int i0 = seg << 8;
            for (int i = i0; i < i0 + 256; i++) {
                float a = zb[((size_t)i << 10) + j] - vec[i];
                if (a > m) { s = s * __expf(m - a) + 1.0f; m = a; }
                else       { s += __expf(a - m); }
            }
            red[t] = m; red2[t] = s;
            __syncthreads();
            if (seg == 0) {
                float m0 = red[jj], m1 = red[jj+64], m2 = red[jj+128], m3 = red[jj+192];
                float M = fmaxf(fmaxf(m0, m1), fmaxf(m2, m3));
                float S = red2[jj]     * __expf(m0 - M) + red2[jj+64]  * __expf(m1 - M)
                        + red2[jj+128] * __expf(m2 - M) + red2[jj+192] * __expf(m3 - M);
                v[(b << 10) + j] = M + __logf(S);
            }
        }
        gridbar_b(b, k);
    }

    for (int i = t; i < 1024; i += 256) vec[i] = v[(b << 10) + i];
    __syncthreads();
    float* pb = P + ((size_t)b << 20);
    #pragma unroll 1
    for (int rr = 0; rr < 8; rr++) {
        int row = (ch << 6) + (w << 3) + rr;
        float uu = u[(b << 10) + row];
        const float* zr = zb + ((size_t)row << 10);
        float* pr = pb + ((size_t)row << 10);
        float s = 0.0f;
        #pragma unroll
        for (int q = 0; q < 8; q++) {
            int idx = lane + (q << 5);
            float4 z4 = ((const float4*)zr)[idx];
            int cb = idx << 2;
            float4 e;
            e.x = __expf(z4.x - uu - vec[cb]);
            e.y = __expf(z4.y - uu - vec[cb+1]);
            e.z = __expf(z4.z - uu - vec[cb+2]);
            e.w = __expf(z4.w - uu - vec[cb+3]);
            ((float4*)pr)[idx] = e;
            s += e.x + e.y + e.z + e.w;
        }
        s = warpSum(s);
        if (lane == 0) r[(b << 10) + row] = s;
    }
    gridbar_b(b, k);

    for (int i = t; i < 1024; i += 256) vec[i] = 1.0f / r[(b << 10) + i];
    __syncthreads();
    {
        int jj = t & 63, seg = t >> 6;
        int j = (ch << 6) + jj;
        float s = 0.0f;
        int i0 = seg << 8;
        for (int i = i0; i < i0 + 256; i++)
            s += pb[((size_t)i << 10) + j] * vec[i];
        red[t] = s;
        __syncthreads();
        if (seg == 0)
            c[(b << 10) + j] = red[jj] + red[jj+64] + red[jj+128] + red[jj+192];
    }
    gridbar_b(b, k);

    for (int i = t; i < 1024; i += 256) vec[i] = c[(b << 10) + i];
    __syncthreads();
    #pragma unroll 1
    for (int rr = 0; rr < 8; rr++) {
        int row = (ch << 6) + (w << 3) + rr;
        float rin = 1.0f / r[(b << 10) + row];
        float* pr = pb + ((size_t)row << 10);
        #pragma unroll
        for (int q = 0; q < 8; q++) {
            int idx = lane + (q << 5);
            float4 p4 = ((float4*)pr)[idx];
            int cb = idx << 2;
            p4.x = p4.x * rin / vec[cb];
            p4.y = p4.y * rin / vec[cb+1];
            p4.z = p4.z * rin / vec[cb+2];
            p4.w = p4.w * rin / vec[cb+3];
            ((float4*)pr)[idx] = p4;
        }
    }
}

// ---------------- launch ----------------
extern "C" void kernel_launch(void* const* d_in, const int* in_sizes, int n_in,
                              void* d_out, int out_size) {
    (void)in_sizes; (void)n_in; (void)out_size;
    const float* X    = (const float*)d_in[0];
    const float* adj  = (const float*)d_in[1];
    const float* w_in = (const float*)d_in[2];
    const float* b_in = (const float*)d_in[3];
    const float* cw1  = (const float*)d_in[4];
    const float* cb1  = (const float*)d_in[5];
    const float* cw2  = (const float*)d_in[6];
    const float* cb2  = (const float*)d_in[7];
    const float* ca   = (const float*)d_in[8];
    const float* m1w  = (const float*)d_in[9];
    const float* m1b  = (const float*)d_in[10];
    const float* m2w  = (const float*)d_in[11];
    const float* m2b  = (const float*)d_in[12];

    float* outP = (float*)d_out;
    float* Z0   = outP + (size_t)NB * NN * NN;

    float *hall, *hcat, *t0, *t1, *t2, *dis, *rsinv, *u, *v, *r, *c;
    __half *adjH, *adjL, *xlH, *xlL, *xsH, *xsL, *p0H, *p0L, *p1H, *p1L, *p2H, *p2L;
    __half *wH, *wL, *xinH, *xinL, *hpH, *hpL, *htH, *htL, *m1H, *m1L, *hcH, *hcL;
    cudaGetSymbolAddress((void**)&hall, g_hall);
    cudaGetSymbolAddress((void**)&hcat, g_hcat);
    cudaGetSymbolAddress((void**)&t0, g_t0);
    cudaGetSymbolAddress((void**)&t1, g_t1);
    cudaGetSymbolAddress((void**)&t2, g_t2);
    cudaGetSymbolAddress((void**)&dis, g_dis);
    cudaGetSymbolAddress((void**)&rsinv, g_rsinv);
    cudaGetSymbolAddress((void**)&u, g_u);
    cudaGetSymbolAddress((void**)&v, g_v);
    cudaGetSymbolAddress((void**)&r, g_r);
    cudaGetSymbolAddress((void**)&c, g_c);
    cudaGetSymbolAddress((void**)&adjH, g_adjH);
    cudaGetSymbolAddress((void**)&adjL, g_adjL);
    cudaGetSymbolAddress((void**)&xlH, g_xlH);
    cudaGetSymbolAddress((void**)&xlL, g_xlL);
    cudaGetSymbolAddress((void**)&xsH, g_xsH);
    cudaGetSymbolAddress((void**)&xsL, g_xsL);
    cudaGetSymbolAddress((void**)&p0H, g_p0H);
    cudaGetSymbolAddress((void**)&p0L, g_p0L);
    cudaGetSymbolAddress((void**)&p1H, g_p1H);
    cudaGetSymbolAddress((void**)&p1L, g_p1L);
    cudaGetSymbolAddress((void**)&p2H, g_p2H);
    cudaGetSymbolAddress((void**)&p2L, g_p2L);
    cudaGetSymbolAddress((void**)&wH, g_wH);
    cudaGetSymbolAddress((void**)&wL, g_wL);
    cudaGetSymbolAddress((void**)&xinH, g_xinH);
    cudaGetSymbolAddress((void**)&xinL, g_xinL);
    cudaGetSymbolAddress((void**)&hpH, g_hpH);
    cudaGetSymbolAddress((void**)&hpL, g_hpL);
    cudaGetSymbolAddress((void**)&htH, g_htH);
    cudaGetSymbolAddress((void**)&htL, g_htL);
    cudaGetSymbolAddress((void**)&m1H, g_m1H);
    cudaGetSymbolAddress((void**)&m1L, g_m1L);
    cudaGetSymbolAddress((void**)&hcH, g_hcH);
    cudaGetSymbolAddress((void**)&hcL, g_hcL);

    const int SMEM_H = 81920;
    cudaFuncSetAttribute(adjmma<1>, cudaFuncAttributeMaxDynamicSharedMemorySize, SMEM_A);
    cudaFuncSetAttribute(adjmma<2>, cudaFuncAttributeMaxDynamicSharedMemorySize, SMEM_A);
    cudaFuncSetAttribute(adjmma<3>, cudaFuncAttributeMaxDynamicSharedMemorySize, SMEM_A);
    cudaFuncSetAttribute(hgemm<0>, cudaFuncAttributeMaxDynamicSharedMemorySize, SMEM_H);
    cudaFuncSetAttribute(hgemm<1>, cudaFuncAttributeMaxDynamicSharedMemorySize, SMEM_H);
    cudaFuncSetAttribute(hgemm<2>, cudaFuncAttributeMaxDynamicSharedMemorySize, SMEM_H);

    const size_t CH = (size_t)NN * HH;

    prep_adj<<<NB * NN, 256>>>(adj, adjH, adjL, dis, rsinv);                // 0
    convert_all<<<11136, 256>>>(cw1, cw2, m1w, m2w, w_in, X,
                                wH, wL, xinH, xinL);                        // 1

    // h0 = X @ w_in^T + b_in -> hcat slice0 + hc pair slice0 + layer-0 xl/xs pairs
    hgemm<0><<<dim3(2, 128), 256, SMEM_H>>>(xinH, xinL, 128,
        wH + OW_WIN, wL + OW_WIN, 128, b_in,
        hcat, LH, hcH, hcL, LH, dis, xlH, xlL, xsH, xsL, nullptr);          // 2

    for (int l = 0; l < 2; l++) {
        const float* Xl = hcat + l * HH;
        // fused: c0 = leaky(A_hat @ Xl)  +  P1 = applyP(Xl), c1 = |Xl - P1|
        adjmma<3><<<dim3(4, 8, NB), 256, SMEM_A>>>(adjH, adjL, xsH, xsL, xlH, xlL,
            Xl, LH, Xl, LH, dis, rsinv, t0, HH, p0H, p0L,
            hall + 0 * CH, hall + 1 * CH);                                  // 3 (l=0)
        // P2 = applyP(P1); c2 = |P1 - P2|
        adjmma<1><<<dim3(2, 8, NB), 256, SMEM_A>>>(adjH, adjL, p0H, p0L, nullptr, nullptr,
            t0, HH, t0, HH, dis, rsinv, t1, HH, p1H, p1L, hall + 2 * CH, nullptr); // 4
        // P3 = applyP(P2)
        adjmma<2><<<dim3(2, 8, NB), 256, SMEM_A>>>(adjH, adjL, p1H, p1L, nullptr, nullptr,
            t1, HH, nullptr, 0, dis, rsinv, t2, HH, p2H, p2L, nullptr, nullptr);   // 5 <-- profiled
        // P4 = applyP(P3); c3 = |P2 - P4|
        adjmma<1><<<dim3(2, 8, NB), 256, SMEM_A>>>(adjH, adjL, p2H, p2L, nullptr, nullptr,
            t2, HH, t1, HH, dis, rsinv, t0, HH, p0H, p0L, hall + 3 * CH, nullptr);

        attention_kernel<<<dim3(NN, NB), 256>>>(Xl, LH, hall, ca + l * 2 * HH, hpH, hpL);

        // conv1: leaky -> ht pair only
        hgemm<1><<<dim3(2, 128), 256, SMEM_H>>>(hpH, hpL, HH,
            wH + OW_CW1 + l * 65536, wL + OW_CW1 + l * 65536, HH, cb1 + l * HH,
            nullptr, 0, htH, htL, HH, nullptr, nullptr, nullptr, nullptr, nullptr, nullptr);
        // conv2: leaky -> hcat slice(l+1) + hc pair slice(l+1) + next-layer xl/xs (l=0 only)
        hgemm<1><<<dim3(2, 128), 256, SMEM_H>>>(htH, htL, HH,
            wH + OW_CW2 + l * 65536, wL + OW_CW2 + l * 65536, HH, cb2 + l * HH,
            hcat + (l + 1) * HH, LH, hcH + (l + 1) * HH, hcL + (l + 1) * HH, LH,
            dis,
            (l == 0) ? xlH : nullptr, (l == 0) ? xlL : nullptr,
            (l == 0) ? xsH : nullptr, (l == 0) ? xsL : nullptr, nullptr);
    }

    // mlp1: leaky -> m1 pair
    hgemm<1><<<dim3(2, 128), 256, SMEM_H>>>(hcH, hcL, LH,
        wH + OW_M1W, wL + OW_M1W, LH, m1b,
        nullptr, 0, m1H, m1L, HH, nullptr, nullptr, nullptr, nullptr, nullptr, nullptr);
    // mlp2 + tanh*40 + gumbel -> Z0
    hgemm<2><<<dim3(8, 128), 256, SMEM_H>>>(m1H, m1L, HH,
        wH + OW_M2W, wL + OW_M2W, HH, m2b,
        nullptr, 0, nullptr, nullptr, 0, nullptr, nullptr, nullptr, nullptr, nullptr, Z0);

    sinkhorn_all<<<NBLK, 256>>>(Z0, outP, u, v, r, c);
}

// round 15
// speedup vs baseline: 1.0681x; 1.0681x over previous
#include <cuda_runtime.h>
#include <cuda_fp16.h>
#include <cstdint>
#include <math.h>

#define NB 16
#define NN 1024
#define HH 256
#define LH 768          // H*(1+L) = 768
#define NBLK 256        // sinkhorn persistent grid

// ---------------- scratch (__device__ globals; no cudaMalloc allowed) ----------------
__device__ float g_hall[(size_t)NB * 4 * NN * HH];   // [b][c][n][h]
__device__ float g_hcat[(size_t)NB * NN * LH];       // [b*n][768]  (h0|h1|h2)
__device__ float g_t0[(size_t)NB * NN * HH];
__device__ float g_t1[(size_t)NB * NN * HH];
__device__ float g_t2[(size_t)NB * NN * HH];
__device__ float g_dis[NB * NN];
__device__ float g_rsinv[NB * NN];
__device__ float g_u[NB * NN];
__device__ float g_v[NB * NN];
__device__ float g_r[NB * NN];
__device__ float g_c[NB * NN];

// fp16 split operands
__device__ __half g_adjH[(size_t)NB * NN * NN];
__device__ __half g_adjL[(size_t)NB * NN * NN];
__device__ __half g_xlH[(size_t)NB * NN * HH];
__device__ __half g_xlL[(size_t)NB * NN * HH];
__device__ __half g_xsH[(size_t)NB * NN * HH];
__device__ __half g_xsL[(size_t)NB * NN * HH];
__device__ __half g_p0H[(size_t)NB * NN * HH];
__device__ __half g_p0L[(size_t)NB * NN * HH];
__device__ __half g_p1H[(size_t)NB * NN * HH];
__device__ __half g_p1L[(size_t)NB * NN * HH];
__device__ __half g_p2H[(size_t)NB * NN * HH];
__device__ __half g_p2L[(size_t)NB * NN * HH];

// fp16 pairs for dense pipeline (+ w_in pack + X pair)
__device__ __half g_wH[753664];
__device__ __half g_wL[753664];
__device__ __half g_xinH[(size_t)NB * NN * 128];
__device__ __half g_xinL[(size_t)NB * NN * 128];
__device__ __half g_hpH[(size_t)NB * NN * HH];
__device__ __half g_hpL[(size_t)NB * NN * HH];
__device__ __half g_htH[(size_t)NB * NN * HH];
__device__ __half g_htL[(size_t)NB * NN * HH];
__device__ __half g_m1H[(size_t)NB * NN * HH];
__device__ __half g_m1L[(size_t)NB * NN * HH];
__device__ __half g_hcH[(size_t)NB * NN * LH];
__device__ __half g_hcL[(size_t)NB * NN * LH];

// per-batch sinkhorn barrier: monotonic arrival counters, reset by prep_adj each call
__device__ unsigned g_arr[16];

#define BSCALE 256.0f
#define BINV   (1.0f / 256.0f)
#define ACCINV (1.0f / 65536.0f)

// weight pack offsets
#define OW_CW1 0
#define OW_CW2 131072
#define OW_M1W 262144
#define OW_M2W 458752
#define OW_WIN 720896
#define W_TOTAL 753664
#define X_TOTAL 2097152

// ---------------- helpers ----------------
__device__ __forceinline__ float lky(float x) { return x > 0.0f ? x : 0.01f * x; }

__device__ __forceinline__ float warpSum(float v) {
    #pragma unroll
    for (int o = 16; o; o >>= 1) v += __shfl_xor_sync(0xffffffffu, v, o);
    return v;
}
__device__ __forceinline__ float warpMax(float v) {
    #pragma unroll
    for (int o = 16; o; o >>= 1) v = fmaxf(v, __shfl_xor_sync(0xffffffffu, v, o));
    return v;
}

__device__ __forceinline__ uint32_t rotl_(uint32_t v, int s) { return (v << s) | (v >> (32 - s)); }

// Threefry-2x32 with key = (0, 42)
__device__ __forceinline__ void threefry_42(uint32_t x0, uint32_t x1, uint32_t& o0, uint32_t& o1) {
    const uint32_t k0 = 0u, k1 = 42u;
    const uint32_t k2 = 0u ^ 42u ^ 0x1BD11BDAu;
    x0 += k0; x1 += k1;
#define TF4(a,b,c,d, ka, kb, inc)                     \
    x0 += x1; x1 = rotl_(x1, a); x1 ^= x0;            \
    x0 += x1; x1 = rotl_(x1, b); x1 ^= x0;            \
    x0 += x1; x1 = rotl_(x1, c); x1 ^= x0;            \
    x0 += x1; x1 = rotl_(x1, d); x1 ^= x0;            \
    x0 += ka; x1 += kb + inc;
    TF4(13, 15, 26, 6,  k1, k2, 1u)
    TF4(17, 29, 16, 24, k2, k0, 2u)
    TF4(13, 15, 26, 6,  k0, k1, 3u)
    TF4(17, 29, 16, 24, k1, k2, 4u)
    TF4(13, 15, 26, 6,  k2, k0, 5u)
#undef TF4
    o0 = x0; o1 = x1;
}

__device__ __forceinline__ float gumbel_noise(uint32_t idx) {
    uint32_t o0, o1;
    threefry_42(0u, idx, o0, o1);
    uint32_t bits = o0 ^ o1;
    float u = __uint_as_float((bits >> 9) | 0x3f800000u) - 1.0f;
    return -logf(-logf(u + 1e-20f) + 1e-20f) * 0.05f;
}

// per-batch grid barrier: monotonic counter; k = barrier index (starts at 1)
__device__ __forceinline__ void gridbar_b(int b, unsigned& k) {
    __syncthreads();
    if (threadIdx.x == 0) {
        __threadfence();
        atomicAdd(&g_arr[b], 1u);
        unsigned target = 16u * k;
        while (*(volatile unsigned*)&g_arr[b] < target) { }
        __threadfence();
    }
    __syncthreads();
    k++;
}

// ---------------- async / mma primitives ----------------
__device__ __forceinline__ uint32_t s2u(const void* p) {
    return (uint32_t)__cvta_generic_to_shared(p);
}
__device__ __forceinline__ void cpa16(uint32_t s, const void* g) {
    asm volatile("cp.async.cg.shared.global [%0], [%1], 16;" :: "r"(s), "l"(g));
}
__device__ __forceinline__ void cpa_commit() {
    asm volatile("cp.async.commit_group;" ::: "memory");
}
template<int N>
__device__ __forceinline__ void cpa_wait() {
    asm volatile("cp.async.wait_group %0;" :: "n"(N) : "memory");
}
__device__ __forceinline__ void ldmA4(uint32_t a, uint32_t* r) {
    asm volatile("ldmatrix.sync.aligned.m8n8.x4.shared.b16 {%0,%1,%2,%3}, [%4];"
        : "=r"(r[0]), "=r"(r[1]), "=r"(r[2]), "=r"(r[3]) : "r"(a));
}
__device__ __forceinline__ void ldmB4T(uint32_t a, uint32_t* r) {
    asm volatile("ldmatrix.sync.aligned.m8n8.x4.trans.shared.b16 {%0,%1,%2,%3}, [%4];"
        : "=r"(r[0]), "=r"(r[1]), "=r"(r[2]), "=r"(r[3]) : "r"(a));
}
__device__ __forceinline__ void mma16816(float* d, const uint32_t* A, const uint32_t* b) {
    asm volatile("mma.sync.aligned.m16n8k16.row.col.f32.f16.f16.f32 "
        "{%0,%1,%2,%3},{%4,%5,%6,%7},{%8,%9},{%0,%1,%2,%3};"
        : "+f"(d[0]), "+f"(d[1]), "+f"(d[2]), "+f"(d[3])
        : "r"(A[0]), "r"(A[1]), "r"(A[2]), "r"(A[3]), "r"(b[0]), "r"(b[1]));
}

// ---------------- fused adj prep: rowsum + fp16 hi/lo conversion + barrier reset ----------------
__global__ void prep_adj(const float* __restrict__ adj,
                         __half* __restrict__ aH, __half* __restrict__ aL,
                         float* __restrict__ dis, float* __restrict__ rsinv) {
    int gr = blockIdx.x, t = threadIdx.x;
    if (gr == 0 && t < 16) g_arr[t] = 0u;    // reset sinkhorn barrier counters (stream-ordered)
    const float* rowp = adj + ((size_t)gr << 10);
    float4 a4 = ((const float4*)rowp)[t];
    __half2 h01 = __floats2half2_rn(a4.x, a4.y);
    __half2 h23 = __floats2half2_rn(a4.z, a4.w);
    __half2 l01 = __floats2half2_rn(a4.x - __low2float(h01), a4.y - __high2float(h01));
    __half2 l23 = __floats2half2_rn(a4.z - __low2float(h23), a4.w - __high2float(h23));
    size_t hb = ((size_t)gr << 9) + ((size_t)t << 1);
    ((__half2*)aH)[hb]     = h01;
    ((__half2*)aH)[hb + 1] = h23;
    ((__half2*)aL)[hb]     = l01;
    ((__half2*)aL)[hb + 1] = l23;
    float s = a4.x + a4.y + a4.z + a4.w;
    s = warpSum(s);
    __shared__ float sm[8];
    if ((t & 31) == 0) sm[t >> 5] = s;
    __syncthreads();
    if (t == 0) {
        float S = sm[0] + sm[1] + sm[2] + sm[3] + sm[4] + sm[5] + sm[6] + sm[7];
        dis[gr]   = rsqrtf(S + 1.0f);
        rsinv[gr] = 1.0f / S;
    }
}

// all weights (incl w_in) + input X -> scaled fp16 pairs, single launch
__global__ void convert_all(const float* __restrict__ cw1, const float* __restrict__ cw2,
                            const float* __restrict__ m1w, const float* __restrict__ m2w,
                            const float* __restrict__ w_in, const float* __restrict__ X,
                            __half* __restrict__ H, __half* __restrict__ L,
                            __half* __restrict__ xinH, __half* __restrict__ xinL) {
    int i = blockIdx.x * 256 + threadIdx.x;
    if (i < W_TOTAL) {
        float x;
        if (i < 131072)      x = cw1[i];
        else if (i < 262144) x = cw2[i - 131072];
        else if (i < 458752) x = m1w[i - 262144];
        else if (i < 720896) x = m2w[i - 458752];
        else                 x = w_in[i - 720896];
        x *= BSCALE;
        __half h = __float2half_rn(x);
        H[i] = h;
        L[i] = __float2half_rn(x - __half2float(h));
    } else {
        int j = i - W_TOTAL;
        float x = X[j] * BSCALE;
        __half h = __float2half_rn(x);
        xinH[j] = h;
        xinL[j] = __float2half_rn(x - __half2float(h));
    }
}

__global__ void convert_pair(const float* __restrict__ src,
                             __half* __restrict__ H, __half* __restrict__ L, int n) {
    int i = blockIdx.x * 256 + threadIdx.x;
    if (i < n) {
        float x = src[i] * BSCALE;
        __half h = __float2half_rn(x);
        H[i] = h;
        L[i] = __float2half_rn(x - __half2float(h));
    }
}

// hcat slice -> xl pair (256*x) and xs pair (256*dis*x)
__global__ void convert_x(const float* __restrict__ Xl, const float* __restrict__ dis,
                          __half* __restrict__ xlH, __half* __restrict__ xlL,
                          __half* __restrict__ xsH, __half* __restrict__ xsL) {
    int gid = blockIdx.x * 256 + threadIdx.x;
    int r = gid >> 8, c = gid & 255;
    float x = Xl[(size_t)r * LH + c];
    float xl = x * BSCALE;
    float xs = xl * dis[r];
    __half h1 = __float2half_rn(xl);
    __half h2 = __float2half_rn(xs);
    xlH[gid] = h1; xlL[gid] = __float2half_rn(xl - __half2float(h1));
    xsH[gid] = h2; xsL[gid] = __float2half_rn(xs - __half2float(h2));
}

// ---------------- tensor-core adjacency GEMM (2-stage, single sync/chunk, occ 2) ----------------
// MODE 1: applyP + diff; MODE 2: applyP plain;
// MODE 3: fused GCN (blockIdx.x<2, B=bH/bL) + applyP-diff (blockIdx.x>=2, B=bH2/bL2).
#define ADJ_STG 37888
#define SMEM_A  (2 * ADJ_STG)

template<int MODE>
__global__ void __launch_bounds__(256, 2)
adjmma(const __half* __restrict__ adjH, const __half* __restrict__ adjL,
       const __half* __restrict__ bH, const __half* __restrict__ bL,
       const __half* __restrict__ bH2, const __half* __restrict__ bL2,
       const float* __restrict__ U32, int ldu,
       const float* __restrict__ aux, int ldaux,
       const float* __restrict__ dis, const float* __restrict__ rsinv,
       float* __restrict__ pout, int ldp,
       __half* __restrict__ poutH, __half* __restrict__ poutL,
       float* __restrict__ hallc, float* __restrict__ hallc2) {
    extern __shared__ char smx[];
    const uint32_t sbase = s2u(smx);
    const int t = threadIdx.x;
    const int b = blockIdx.z;
    const int m0 = blockIdx.y << 7;
    const int sel = (MODE == 3) ? ((int)blockIdx.x >> 1) : 0;
    const int n0 = ((MODE == 3) ? ((int)blockIdx.x & 1) : (int)blockIdx.x) << 7;
    const __half* BHp = (MODE == 3 && sel) ? bH2 : bH;
    const __half* BLp = (MODE == 3 && sel) ? bL2 : bL;
    const int w = t >> 5, lane = t & 31;
    const int wm = w >> 1, wn = w & 1;
    const int lr16 = lane & 15, lhi = lane >> 4;

    float acc[2][8][4];
    #pragma unroll
    for (int mi = 0; mi < 2; mi++)
        #pragma unroll
        for (int nj = 0; nj < 8; nj++)
            #pragma unroll
            for (int ci = 0; ci < 4; ci++) acc[mi][nj][ci] = 0.0f;

    const int ar = t >> 2,  asg = t & 3;
    const int bk = t >> 4,  bsg = t & 15;

    auto issue = [&](int kt, int st) {
        uint32_t AHb = sbase + st * ADJ_STG;
        uint32_t ALb = AHb + 10240;
        uint32_t BHb = ALb + 10240;
        uint32_t BLb = BHb + 8704;
        #pragma unroll
        for (int it = 0; it < 2; it++) {
            int r = ar + (it << 6);
            size_t gA = ((size_t)b << 20) + ((size_t)(m0 + r) << 10) + (kt << 5) + (asg << 3);
            uint32_t sA = (uint32_t)(r * 80 + (asg << 4));
            cpa16(AHb + sA, adjH + gA);
            cpa16(ALb + sA, adjL + gA);
            int k = bk + (it << 4);
            size_t gB = ((size_t)((b << 10) + (kt << 5) + k) << 8) + n0 + (bsg << 3);
            uint32_t sB = (uint32_t)(k * 272 + (bsg << 4));
            cpa16(BHb + sB, BHp + gB);
            cpa16(BLb + sB, BLp + gB);
        }
        cpa_commit();
    };

    issue(0, 0);
    for (int kt = 0; kt < 32; kt++) {
        cpa_wait<0>();
        __syncthreads();
        if (kt + 1 < 32) issue(kt + 1, (kt + 1) & 1);

        int st = kt & 1;
        uint32_t AHb = sbase + st * ADJ_STG;
        uint32_t ALb = AHb + 10240;
        uint32_t BHb = ALb + 10240;
        uint32_t BLb = BHb + 8704;

        #pragma unroll
        for (int kk = 0; kk < 32; kk += 16) {
            uint32_t aHf[2][4], aLf[2][4];
            uint32_t cc2 = (uint32_t)((kk + (lhi << 3)) << 1);
            #pragma unroll
            for (int mi = 0; mi < 2; mi++) {
                uint32_t ro = (uint32_t)((wm * 32 + mi * 16 + lr16) * 80);
                ldmA4(AHb + ro + cc2, aHf[mi]);
                ldmA4(ALb + ro + cc2, aLf[mi]);
            }
            #pragma unroll
            for (int hf = 0; hf < 2; hf++) {
                uint32_t bHf[4][2], bLf[4][2];
                #pragma unroll
                for (int np = 0; np < 2; np++) {
                    uint32_t ko = (uint32_t)((kk + lr16) * 272);
                    uint32_t nc = (uint32_t)((wn * 64 + hf * 32 + np * 16 + (lhi << 3)) << 1);
                    uint32_t r4[4];
                    ldmB4T(BHb + ko + nc, r4);
                    bHf[np*2][0] = r4[0]; bHf[np*2][1] = r4[1];
                    bHf[np*2+1][0] = r4[2]; bHf[np*2+1][1] = r4[3];
                    ldmB4T(BLb + ko + nc, r4);
                    bLf[np*2][0] = r4[0]; bLf[np*2][1] = r4[1];
                    bLf[np*2+1][0] = r4[2]; bLf[np*2+1][1] = r4[3];
                }
                #pragma unroll
                for (int mi = 0; mi < 2; mi++)
                    #pragma unroll
                    for (int nj = 0; nj < 4; nj++) {
                        float* ac = acc[mi][hf * 4 + nj];
                        mma16816(ac, aHf[mi], bHf[nj]);
                        mma16816(ac, aHf[mi], bLf[nj]);
                        mma16816(ac, aLf[mi], bHf[nj]);
                    }
            }
        }
    }

    const int g8 = lane >> 2, t4 = lane & 3;
    #pragma unroll
    for (int mi = 0; mi < 2; mi++)
        #pragma unroll
        for (int nj = 0; nj < 8; nj++)
            #pragma unroll
            for (int ci = 0; ci < 4; ci++) {
                int il = m0 + wm * 32 + mi * 16 + g8 + ((ci >> 1) << 3);
                int cg = n0 + wn * 64 + nj * 8 + (t4 << 1) + (ci & 1);
                int gi = (b << 10) + il;
                float a = acc[mi][nj][ci] * BINV;
                size_t hix = ((size_t)b << 20) + ((size_t)il << 8) + cg;
                if (MODE == 3 && sel == 0) {
                    float di = dis[gi];
                    float xv = aux[(size_t)gi * ldaux + cg];
                    hallc[hix] = lky(di * a + di * di * xv);
                } else {
                    float p = 0.5f * (U32[(size_t)gi * ldu + cg] + rsinv[gi] * a);
                    pout[(size_t)gi * ldp + cg] = p;
                    float ps = p * BSCALE;
                    __half ph = __float2half_rn(ps);
                    size_t pix = ((size_t)gi << 8) + cg;
                    poutH[pix] = ph;
                    poutL[pix] = __float2half_rn(ps - __half2float(ph));
                    if (MODE == 1) {
                        float ax = aux[(size_t)gi * ldaux + cg];
                        hallc[hix] = fabsf(ax - p);
                    } else if (MODE == 3) {
                        float ax = aux[(size_t)gi * ldaux + cg];
                        hallc2[hix] = fabsf(ax - p);
                    }
                }
            }
}

// ---------------- dense HMMA GEMM (single sync/chunk) ----------------
// EP 0: raw out; EP 1: leaky -> optional fp32 out + optional fp16 pair; EP 2: Z0 epilogue.
template<int EP>
__global__ void __launch_bounds__(256, 2)
hgemm(const __half* __restrict__ AH, const __half* __restrict__ AL, int lda,
      const __half* __restrict__ WH, const __half* __restrict__ WL, int K,
      const float* __restrict__ bias,
      float* __restrict__ out, int ldo,
      __half* __restrict__ poH, __half* __restrict__ poL, int ldp,
      float* __restrict__ zbuf) {
    extern __shared__ char smx[];
    const uint32_t sbase = s2u(smx);
    const int t = threadIdx.x;
    const int m0 = blockIdx.y << 7;
    const int n0 = blockIdx.x << 7;
    const int w = t >> 5, lane = t & 31;
    const int wm = w >> 1, wn = w & 1;
    const int lr16 = lane & 15, lhi = lane >> 4;

    float acc[2][8][4];
    #pragma unroll
    for (int mi = 0; mi < 2; mi++)
        #pragma unroll
        for (int nj = 0; nj < 8; nj++)
            #pragma unroll
            for (int ci = 0; ci < 4; ci++) acc[mi][nj][ci] = 0.0f;

    const int lrow = t >> 1, lsg = t & 1;

    auto issue = [&](int kt, int st) {
        uint32_t AHb = sbase + st * 40960;
        uint32_t ALb = AHb + 10240;
        uint32_t WHb = ALb + 10240;
        uint32_t WLb = WHb + 10240;
        uint32_t so = (uint32_t)(lrow * 80 + (lsg << 5));
        size_t gA = (size_t)(m0 + lrow) * lda + (kt << 5) + (lsg << 4);
        size_t gW = (size_t)(n0 + lrow) * K   + (kt << 5) + (lsg << 4);
        cpa16(AHb + so,      AH + gA);
        cpa16(AHb + so + 16, AH + gA + 8);
        cpa16(ALb + so,      AL + gA);
        cpa16(ALb + so + 16, AL + gA + 8);
        cpa16(WHb + so,      WH + gW);
        cpa16(WHb + so + 16, WH + gW + 8);
        cpa16(WLb + so,      WL + gW);
        cpa16(WLb + so + 16, WL + gW + 8);
        cpa_commit();
    };

    const int nchunks = K >> 5;
    issue(0, 0);
    for (int kt = 0; kt < nchunks; kt++) {
        cpa_wait<0>();
        __syncthreads();
        if (kt + 1 < nchunks) issue(kt + 1, (kt + 1) & 1);

        int st = kt & 1;
        uint32_t AHb = sbase + st * 40960;
        uint32_t ALb = AHb + 10240;
        uint32_t WHb = ALb + 10240;
        uint32_t WLb = WHb + 10240;

        #pragma unroll
        for (int kk = 0; kk < 32; kk += 16) {
            uint32_t aHf[2][4], aLf[2][4];
            uint32_t cc2 = (uint32_t)((kk + (lhi << 3)) << 1);
            #pragma unroll
            for (int mi = 0; mi < 2; mi++) {
                uint32_t ro = (uint32_t)((wm * 32 + mi * 16 + lr16) * 80);
                ldmA4(AHb + ro + cc2, aHf[mi]);
                ldmA4(ALb + ro + cc2, aLf[mi]);
            }
            uint32_t nrow = (uint32_t)(((lane >> 4) << 3) + (lane & 7));
            uint32_t kb   = (uint32_t)(kk * 2 + ((lane >> 3) & 1) * 16);
            #pragma unroll
            for (int hf = 0; hf < 2; hf++) {
                uint32_t bHf[4][2], bLf[4][2];
                #pragma unroll
                for (int np = 0; np < 2; np++) {
                    uint32_t ad = (uint32_t)((wn * 64 + hf * 32 + np * 16 + nrow) * 80) + kb;
                    uint32_t r4[4];
                    ldmA4(WHb + ad, r4);
                    bHf[np*2][0] = r4[0]; bHf[np*2][1] = r4[1];
                    bHf[np*2+1][0] = r4[2]; bHf[np*2+1][1] = r4[3];
                    ldmA4(WLb + ad, r4);
                    bLf[np*2][0] = r4[0]; bLf[np*2][1] = r4[1];
                    bLf[np*2+1][0] = r4[2]; bLf[np*2+1][1] = r4[3];
                }
                #pragma unroll
                for (int mi = 0; mi < 2; mi++)
                    #pragma unroll
                    for (int nj = 0; nj < 4; nj++) {
                        float* ac = acc[mi][hf * 4 + nj];
                        mma16816(ac, aHf[mi], bHf[nj]);
                        mma16816(ac, aHf[mi], bLf[nj]);
                        mma16816(ac, aLf[mi], bHf[nj]);
                    }
            }
        }
    }

    const int g8 = lane >> 2, t4 = lane & 3;
    #pragma unroll
    for (int mi = 0; mi < 2; mi++)
        #pragma unroll
        for (int nj = 0; nj < 8; nj++)
            #pragma unroll
            for (int ci = 0; ci < 4; ci++) {
                int rg = m0 + wm * 32 + mi * 16 + g8 + ((ci >> 1) << 3);
                int cg = n0 + wn * 64 + nj * 8 + (t4 << 1) + (ci & 1);
                float v = acc[mi][nj][ci] * ACCINV + __ldg(&bias[cg]);
                if (EP == 0) {
                    out[(size_t)rg * ldo + cg] = v;
                } else if (EP == 1) {
                    float o = lky(v);
                    if (out) out[(size_t)rg * ldo + cg] = o;
                    if (poH) {
                        float ps = o * BSCALE;
                        __half ph = __float2half_rn(ps);
                        size_t pix = (size_t)rg * ldp + cg;
                        poH[pix] = ph;
                        poL[pix] = __float2half_rn(ps - __half2float(ph));
                    }
                } else {
                    uint32_t idx = ((uint32_t)rg << 10) + (uint32_t)cg;
                    float z = (tanhf(v) * 40.0f + gumbel_noise(idx)) * 10.0f;
                    zbuf[idx] = z;
                }
            }
}

// ---------------- attention + channel mix -> hp fp16 pair ----------------
__global__ void attention_kernel(const float* __restrict__ Xl, int ldx,
                                 const float* __restrict__ hall,
                                 const float* __restrict__ a,
                                 __half* __restrict__ hpH, __half* __restrict__ hpL) {
    int n = blockIdx.x, b = blockIdx.y, t = threadIdx.x;
    float xv = Xl[(size_t)((b << 10) + n) * ldx + t];
    float hv[4];
    size_t hbase = ((size_t)b << 20) + ((size_t)n << 8) + t;
    #pragma unroll
    for (int c = 0; c < 4; c++) hv[c] = hall[hbase + ((size_t)c << 18)];
    float a1 = a[t], a2 = a[256 + t];
    float p[5];
    p[0] = fmaxf(xv, 0.0f) * a1;
    #pragma unroll
    for (int c = 0; c < 4; c++) p[1 + c] = fmaxf(hv[c], 0.0f) * a2;

    __shared__ float sm[5][8];
    #pragma unroll
    for (int q = 0; q < 5; q++) {
        float s = warpSum(p[q]);
        if ((t & 31) == 0) sm[q][t >> 5] = s;
    }
    __syncthreads();
    float S[5];
    #pragma unroll
    for (int q = 0; q < 5; q++) {
        float s = sm[q][0];
        #pragma unroll
        for (int w = 1; w < 8; w++) s += sm[q][w];
        S[q] = s;
    }
    float e0 = S[0] + S[1], e1 = S[0] + S[2], e2 = S[0] + S[3], e3 = S[0] + S[4];
    float M = fmaxf(fmaxf(e0, e1), fmaxf(e2, e3));
    float w0 = __expf(e0 - M), w1 = __expf(e1 - M), w2 = __expf(e2 - M), w3 = __expf(e3 - M);
    float ws = w0 + w1 + w2 + w3;
    float o = w0 * hv[0] + w1 * hv[1] + w2 * hv[2] + w3 * hv[3];
    float hpv = 0.25f * o / ws;
    float ps = hpv * BSCALE;
    __half ph = __float2half_rn(ps);
    size_t pix = (size_t)((b << 10) + n) * HH + t;
    hpH[pix] = ph;
    hpL[pix] = __float2half_rn(ps - __half2float(ph));
}

// ---------------- persistent sinkhorn (per-batch monotonic barriers) ----------------
__global__ void __launch_bounds__(256)
sinkhorn_all(const float* __restrict__ Z0, float* __restrict__ P,
             float* __restrict__ u, float* __restrict__ v,
             float* __restrict__ r, float* __restrict__ c) {
    const int t = threadIdx.x;
    const int bid = blockIdx.x;
    const int b = bid >> 4, ch = bid & 15;
    const int lane = t & 31, w = t >> 5;
    __shared__ float vec[1024];
    __shared__ float red[256];
    __shared__ float red2[256];
    unsigned k = 1;

    if (t < 64) {
        u[(b << 10) + (ch << 6) + t] = 0.0f;
        v[(b << 10) + (ch << 6) + t] = 0.0f;
    }
    gridbar_b(b, k);

    const float* zb = Z0 + ((size_t)b << 20);

    for (int it = 0; it < 20; it++) {
        for (int i = t; i < 1024; i += 256) vec[i] = v[(b << 10) + i];
        __syncthreads();
        #pragma unroll 1
        for (int rr = 0; rr < 8; rr++) {
            int row = (ch << 6) + (w << 3) + rr;
            const float* zr = zb + ((size_t)row << 10);
            float a[32];
            float m = -INFINITY;
            #pragma unroll
            for (int q = 0; q < 8; q++) {
                int idx = lane + (q << 5);
                float4 z4 = ((const float4*)zr)[idx];
                int cb = idx << 2;
                a[q*4+0] = z4.x - vec[cb];
                a[q*4+1] = z4.y - vec[cb+1];
                a[q*4+2] = z4.z - vec[cb+2];
                a[q*4+3] = z4.w - vec[cb+3];
                m = fmaxf(m, fmaxf(fmaxf(a[q*4], a[q*4+1]), fmaxf(a[q*4+2], a[q*4+3])));
            }
            m = warpMax(m);
            float s = 0.0f;
            #pragma unroll
            for (int q = 0; q < 32; q++) s += __expf(a[q] - m);
            s = warpSum(s);
            if (lane == 0) u[(b << 10) + row] = m + __logf(s);
        }
        gridbar_b(b, k);

        for (int i = t; i < 1024; i += 256) vec[i] = u[(b << 10) + i];
        __syncthreads();
        {
            int jj = t & 63, seg = t >> 6;
            int j = (ch << 6) + jj;
            float m = -INFINITY, s = 0.0f;
            int i0 = seg << 8;
            for (int i = i0; i < i0 + 256; i++) {
                float a = zb[((size_t)i << 10) + j] - vec[i];
                if (a > m) { s = s * __expf(m - a) + 1.0f; m = a; }
                else       { s += __expf(a - m); }
            }
            red[t] = m; red2[t] = s;
            __syncthreads();
            if (seg == 0) {
                float m0 = red[jj], m1 = red[jj+64], m2 = red[jj+128], m3 = red[jj+192];
                float M = fmaxf(fmaxf(m0, m1), fmaxf(m2, m3));
                float S = red2[jj]     * __expf(m0 - M) + red2[jj+64]  * __expf(m1 - M)
                        + red2[jj+128] * __expf(m2 - M) + red2[jj+192] * __expf(m3 - M);
                v[(b << 10) + j] = M + __logf(S);
            }
        }
        gridbar_b(b, k);
    }

    for (int i = t; i < 1024; i += 256) vec[i] = v[(b << 10) + i];
    __syncthreads();
    float* pb = P + ((size_t)b << 20);
    #pragma unroll 1
    for (int rr = 0; rr < 8; rr++) {
        int row = (ch << 6) + (w << 3) + rr;
        float uu = u[(b << 10) + row];
        const float* zr = zb + ((size_t)row << 10);
        float* pr = pb + ((size_t)row << 10);
        float s = 0.0f;
        #pragma unroll
        for (int q = 0; q < 8; q++) {
            int idx = lane + (q << 5);
            float4 z4 = ((const float4*)zr)[idx];
            int cb = idx << 2;
            float4 e;
            e.x = __expf(z4.x - uu - vec[cb]);
            e.y = __expf(z4.y - uu - vec[cb+1]);
            e.z = __expf(z4.z - uu - vec[cb+2]);
            e.w = __expf(z4.w - uu - vec[cb+3]);
            ((float4*)pr)[idx] = e;
            s += e.x + e.y + e.z + e.w;
        }
        s = warpSum(s);
        if (lane == 0) r[(b << 10) + row] = s;
    }
    gridbar_b(b, k);

    for (int i = t; i < 1024; i += 256) vec[i] = 1.0f / r[(b << 10) + i];
    __syncthreads();
    {
        int jj = t & 63, seg = t >> 6;
        int j = (ch << 6) + jj;
        float s = 0.0f;
        int i0 = seg << 8;
        for (int i = i0; i < i0 + 256; i++)
            s += pb[((size_t)i << 10) + j] * vec[i];
        red[t] = s;
        __syncthreads();
        if (seg == 0)
            c[(b << 10) + j] = red[jj] + red[jj+64] + red[jj+128] + red[jj+192];
    }
    gridbar_b(b, k);

    for (int i = t; i < 1024; i += 256) vec[i] = c[(b << 10) + i];
    __syncthreads();
    #pragma unroll 1
    for (int rr = 0; rr < 8; rr++) {
        int row = (ch << 6) + (w << 3) + rr;
        float rin = 1.0f / r[(b << 10) + row];
        float* pr = pb + ((size_t)row << 10);
        #pragma unroll
        for (int q = 0; q < 8; q++) {
            int idx = lane + (q << 5);
            float4 p4 = ((float4*)pr)[idx];
            int cb = idx << 2;
            p4.x = p4.x * rin / vec[cb];
            p4.y = p4.y * rin / vec[cb+1];
            p4.z = p4.z * rin / vec[cb+2];
            p4.w = p4.w * rin / vec[cb+3];
            ((float4*)pr)[idx] = p4;
        }
    }
}

// ---------------- launch ----------------
extern "C" void kernel_launch(void* const* d_in, const int* in_sizes, int n_in,
                              void* d_out, int out_size) {
    (void)in_sizes; (void)n_in; (void)out_size;
    const float* X    = (const float*)d_in[0];
    const float* adj  = (const float*)d_in[1];
    const float* w_in = (const float*)d_in[2];
    const float* b_in = (const float*)d_in[3];
    const float* cw1  = (const float*)d_in[4];
    const float* cb1  = (const float*)d_in[5];
    const float* cw2  = (const float*)d_in[6];
    const float* cb2  = (const float*)d_in[7];
    const float* ca   = (const float*)d_in[8];
    const float* m1w  = (const float*)d_in[9];
    const float* m1b  = (const float*)d_in[10];
    const float* m2w  = (const float*)d_in[11];
    const float* m2b  = (const float*)d_in[12];

    float* outP = (float*)d_out;
    float* Z0   = outP + (size_t)NB * NN * NN;

    float *hall, *hcat, *t0, *t1, *t2, *dis, *rsinv, *u, *v, *r, *c;
    __half *adjH, *adjL, *xlH, *xlL, *xsH, *xsL, *p0H, *p0L, *p1H, *p1L, *p2H, *p2L;
    __half *wH, *wL, *xinH, *xinL, *hpH, *hpL, *htH, *htL, *m1H, *m1L, *hcH, *hcL;
    cudaGetSymbolAddress((void**)&hall, g_hall);
    cudaGetSymbolAddress((void**)&hcat, g_hcat);
    cudaGetSymbolAddress((void**)&t0, g_t0);
    cudaGetSymbolAddress((void**)&t1, g_t1);
    cudaGetSymbolAddress((void**)&t2, g_t2);
    cudaGetSymbolAddress((void**)&dis, g_dis);
    cudaGetSymbolAddress((void**)&rsinv, g_rsinv);
    cudaGetSymbolAddress((void**)&u, g_u);
    cudaGetSymbolAddress((void**)&v, g_v);
    cudaGetSymbolAddress((void**)&r, g_r);
    cudaGetSymbolAddress((void**)&c, g_c);
    cudaGetSymbolAddress((void**)&adjH, g_adjH);
    cudaGetSymbolAddress((void**)&adjL, g_adjL);
    cudaGetSymbolAddress((void**)&xlH, g_xlH);
    cudaGetSymbolAddress((void**)&xlL, g_xlL);
    cudaGetSymbolAddress((void**)&xsH, g_xsH);
    cudaGetSymbolAddress((void**)&xsL, g_xsL);
    cudaGetSymbolAddress((void**)&p0H, g_p0H);
    cudaGetSymbolAddress((void**)&p0L, g_p0L);
    cudaGetSymbolAddress((void**)&p1H, g_p1H);
    cudaGetSymbolAddress((void**)&p1L, g_p1L);
    cudaGetSymbolAddress((void**)&p2H, g_p2H);
    cudaGetSymbolAddress((void**)&p2L, g_p2L);
    cudaGetSymbolAddress((void**)&wH, g_wH);
    cudaGetSymbolAddress((void**)&wL, g_wL);
    cudaGetSymbolAddress((void**)&xinH, g_xinH);
    cudaGetSymbolAddress((void**)&xinL, g_xinL);
    cudaGetSymbolAddress((void**)&hpH, g_hpH);
    cudaGetSymbolAddress((void**)&hpL, g_hpL);
    cudaGetSymbolAddress((void**)&htH, g_htH);
    cudaGetSymbolAddress((void**)&htL, g_htL);
    cudaGetSymbolAddress((void**)&m1H, g_m1H);
    cudaGetSymbolAddress((void**)&m1L, g_m1L);
    cudaGetSymbolAddress((void**)&hcH, g_hcH);
    cudaGetSymbolAddress((void**)&hcL, g_hcL);

    const int SMEM_H = 81920;
    cudaFuncSetAttribute(adjmma<1>, cudaFuncAttributeMaxDynamicSharedMemorySize, SMEM_A);
    cudaFuncSetAttribute(adjmma<2>, cudaFuncAttributeMaxDynamicSharedMemorySize, SMEM_A);
    cudaFuncSetAttribute(adjmma<3>, cudaFuncAttributeMaxDynamicSharedMemorySize, SMEM_A);
    cudaFuncSetAttribute(hgemm<0>, cudaFuncAttributeMaxDynamicSharedMemorySize, SMEM_H);
    cudaFuncSetAttribute(hgemm<1>, cudaFuncAttributeMaxDynamicSharedMemorySize, SMEM_H);
    cudaFuncSetAttribute(hgemm<2>, cudaFuncAttributeMaxDynamicSharedMemorySize, SMEM_H);

    const size_t CH = (size_t)NN * HH;

    prep_adj<<<NB * NN, 256>>>(adj, adjH, adjL, dis, rsinv);                // 0
    convert_all<<<11136, 256>>>(cw1, cw2, m1w, m2w, w_in, X,
                                wH, wL, xinH, xinL);                        // 1

    // h0 = X @ w_in^T + b_in  -> hcat slice 0 (ld 768)
    hgemm<0><<<dim3(2, 128), 256, SMEM_H>>>(xinH, xinL, 128,
        wH + OW_WIN, wL + OW_WIN, 128, b_in,
        hcat, LH, nullptr, nullptr, 0, nullptr);                            // 2

    for (int l = 0; l < 2; l++) {
        const float* Xl = hcat + l * HH;
        convert_x<<<16384, 256>>>(Xl, dis, xlH, xlL, xsH, xsL);             // 3
        // fused: c0 = leaky(A_hat @ Xl)  +  P1 = applyP(Xl), c1 = |Xl - P1|
        adjmma<3><<<dim3(4, 8, NB), 256, SMEM_A>>>(adjH, adjL, xsH, xsL, xlH, xlL,
            Xl, LH, Xl, LH, dis, rsinv, t0, HH, p0H, p0L,
            hall + 0 * CH, hall + 1 * CH);                                  // 4
        // P2 = applyP(P1); c2 = |P1 - P2|
        adjmma<1><<<dim3(2, 8, NB), 256, SMEM_A>>>(adjH, adjL, p0H, p0L, nullptr, nullptr,
            t0, HH, t0, HH, dis, rsinv, t1, HH, p1H, p1L, hall + 2 * CH, nullptr); // 5 <-- profiled
        // P3 = applyP(P2)
        adjmma<2><<<dim3(2, 8, NB), 256, SMEM_A>>>(adjH, adjL, p1H, p1L, nullptr, nullptr,
            t1, HH, nullptr, 0, dis, rsinv, t2, HH, p2H, p2L, nullptr, nullptr);
        // P4 = applyP(P3); c3 = |P2 - P4|
        adjmma<1><<<dim3(2, 8, NB), 256, SMEM_A>>>(adjH, adjL, p2H, p2L, nullptr, nullptr,
            t2, HH, t1, HH, dis, rsinv, t0, HH, p0H, p0L, hall + 3 * CH, nullptr);

        attention_kernel<<<dim3(NN, NB), 256>>>(Xl, LH, hall, ca + l * 2 * HH, hpH, hpL);

        hgemm<1><<<dim3(2, 128), 256, SMEM_H>>>(hpH, hpL, HH,
            wH + OW_CW1 + l * 65536, wL + OW_CW1 + l * 65536, HH, cb1 + l * HH,
            nullptr, 0, htH, htL, HH, nullptr);
        hgemm<1><<<dim3(2, 128), 256, SMEM_H>>>(htH, htL, HH,
            wH + OW_CW2 + l * 65536, wL + OW_CW2 + l * 65536, HH, cb2 + l * HH,
            hcat + (l + 1) * HH, LH, nullptr, nullptr, 0, nullptr);
    }

    convert_pair<<<49152, 256>>>(hcat, hcH, hcL, 16384 * LH);
    hgemm<1><<<dim3(2, 128), 256, SMEM_H>>>(hcH, hcL, LH,
        wH + OW_M1W, wL + OW_M1W, LH, m1b,
        nullptr, 0, m1H, m1L, HH, nullptr);
    hgemm<2><<<dim3(8, 128), 256, SMEM_H>>>(m1H, m1L, HH,
        wH + OW_M2W, wL + OW_M2W, HH, m2b,
        nullptr, 0, nullptr, nullptr, 0, Z0);

    sinkhorn_all<<<NBLK, 256>>>(Z0, outP, u, v, r, c);
}